// round 14
// baseline (speedup 1.0000x reference)
#include <cuda_runtime.h>
#include <cuda_bf16.h>
#include <cstdint>

// ---------------- problem constants ----------------
#define N_NODES   100000
#define E_EDGES   600000
#define RELS      20
#define D         128
#define TILE_E    128
#define MAX_TILES ((E_EDGES + TILE_E - 1) / TILE_E + RELS)   // 4708
#define ROOT_TILES ((N_NODES + TILE_E - 1) / TILE_E)          // 782

// smem word layout (uint32 words), stride 68 words per row (136 bf16)
#define SM_AHI    0
#define SM_ALO    8704
#define SM_WHI    17408
#define SM_WLO    26112
#define SM_DST    34816
#define SM_INV    34944
#define SM_BIAS   35072
#define SM_SRC    35200
#define SMEM_WORDS 35328
#define SMEM_BYTES (SMEM_WORDS * 4)  // 141312
#define OSTR      132                // output bounce stride (fp32 words)

// mega-kernel block ranges
#define CB  2344     // count: ceil(E/256)
#define GB  50000    // gather+split emb: N*D/256
#define WB  1280     // wsplit per W tensor: 20*16384/256
#define RB  64       // wsplit per root tensor: 16384/256
#define MEGA_BLOCKS (CB + GB + 2*WB + 2*RB)   // 55032

// ---------------- device scratch ----------------
// activations stored pre-split: per node 256 bf16 = [0:128) hi | [128:256) lo
__device__ __nv_bfloat16 g_hs0[(size_t)N_NODES * 256];  // layer-1 input
__device__ float         g_buf[(size_t)N_NODES * D];    // layer-1 fp32 accumulator
__device__ __nv_bfloat16 g_hs1[(size_t)N_NODES * 256];  // relu(buf) split
__device__ float g_invc[(size_t)RELS * N_NODES];
__device__ int   g_cnt [(size_t)RELS * N_NODES];
__device__ int   g_hist[RELS];
__device__ int   g_relStart[RELS + 1];
__device__ int   g_cursor[RELS];
__device__ unsigned g_ticket;
__device__ int   g_perm[E_EDGES];
__device__ int   g_tileRel[MAX_TILES];
__device__ int   g_tileOff[MAX_TILES];
__device__ int   g_tileCnt[MAX_TILES];

// split-bf16 weights, transposed to [n][k] for col-major B fragments
__device__ __nv_bfloat16 g_w1hi[(size_t)RELS * D * D];
__device__ __nv_bfloat16 g_w1lo[(size_t)RELS * D * D];
__device__ __nv_bfloat16 g_w2hi[(size_t)RELS * D * D];
__device__ __nv_bfloat16 g_w2lo[(size_t)RELS * D * D];
__device__ __nv_bfloat16 g_r1hi[D * D];
__device__ __nv_bfloat16 g_r1lo[D * D];
__device__ __nv_bfloat16 g_r2hi[D * D];
__device__ __nv_bfloat16 g_r2lo[D * D];

// ---------------- helpers ----------------
__device__ __forceinline__ void splitf(float v, __nv_bfloat16& h, __nv_bfloat16& l) {
    h = __float2bfloat16_rn(v);
    l = __float2bfloat16_rn(v - __bfloat162float(h));
}

__device__ __forceinline__ void wsplit_one(const float* __restrict__ w,
                                           __nv_bfloat16* __restrict__ hi,
                                           __nv_bfloat16* __restrict__ lo, int idx) {
    int m = idx >> 14;
    int rem = idx & 16383;
    int k = rem >> 7;
    int n = rem & 127;
    float v = w[(size_t)m * 16384 + k * 128 + n];
    __nv_bfloat16 h, l;
    splitf(v, h, l);
    size_t dst = (size_t)m * 16384 + n * 128 + k;
    hi[dst] = h;
    lo[dst] = l;
}

// ---------------- launch 0: mega preprocessing ----------------
__global__ void __launch_bounds__(256) k_mega(const int* __restrict__ x,
                                              const float* __restrict__ emb,
                                              const int* __restrict__ etype,
                                              const int* __restrict__ dst,
                                              const float* __restrict__ w1,
                                              const float* __restrict__ w2,
                                              const float* __restrict__ r1,
                                              const float* __restrict__ r2) {
    __shared__ int sh[RELS];
    int b = blockIdx.x;
    if (b < CB) {
        // per-(rel,dst) counts + per-rel histogram
        if (threadIdx.x < RELS) sh[threadIdx.x] = 0;
        __syncthreads();
        int e = b * 256 + threadIdx.x;
        if (e < E_EDGES) {
            int r = etype[e];
            atomicAdd(&g_cnt[(size_t)r * N_NODES + dst[e]], 1);
            atomicAdd(&sh[r], 1);
        }
        __syncthreads();
        if (threadIdx.x < RELS) atomicAdd(&g_hist[threadIdx.x], sh[threadIdx.x]);
    } else if (b < CB + GB) {
        // gather emb by x, split to bf16 hi/lo
        int idx = (b - CB) * 256 + threadIdx.x;     // < N*D exactly
        int node = idx >> 7, k = idx & 127;
        float v = emb[(size_t)x[node] * D + k];
        __nv_bfloat16 h, l;
        splitf(v, h, l);
        g_hs0[(size_t)node * 256 + k]       = h;
        g_hs0[(size_t)node * 256 + 128 + k] = l;
    } else if (b < CB + GB + WB) {
        wsplit_one(w1, g_w1hi, g_w1lo, (b - CB - GB) * 256 + threadIdx.x);
    } else if (b < CB + GB + 2 * WB) {
        wsplit_one(w2, g_w2hi, g_w2lo, (b - CB - GB - WB) * 256 + threadIdx.x);
    } else if (b < CB + GB + 2 * WB + RB) {
        wsplit_one(r1, g_r1hi, g_r1lo, (b - CB - GB - 2 * WB) * 256 + threadIdx.x);
    } else {
        wsplit_one(r2, g_r2hi, g_r2lo, (b - CB - GB - 2 * WB - RB) * 256 + threadIdx.x);
    }
}

// ---------------- launch 1: invc + (last block) scan + tile table ----------------
__global__ void __launch_bounds__(256) k_inv_scan() {
    __shared__ bool isLast;
    int i = blockIdx.x * 256 + threadIdx.x;
    if (i < RELS * N_NODES) {
        int c = g_cnt[i];
        g_invc[i] = 1.0f / (float)(c > 1 ? c : 1);
        g_cnt[i] = 0;                               // re-zero for next replay
    }
    __threadfence();
    if (threadIdx.x == 0) {
        unsigned t = atomicAdd(&g_ticket, 1u);
        isLast = (t == gridDim.x - 1);
    }
    __syncthreads();
    if (!isLast) return;

    __shared__ int base[RELS + 1];
    if (threadIdx.x == 0) {
        int bsum = 0;
        for (int r = 0; r < RELS; r++) {
            g_relStart[r] = bsum;
            bsum += g_hist[r];
            g_cursor[r] = 0;
            g_hist[r] = 0;                          // re-zero for next replay
        }
        g_relStart[RELS] = bsum;
        int tb = 0;
        for (int r = 0; r < RELS; r++) {
            base[r] = tb;
            int seg = g_relStart[r + 1] - g_relStart[r];
            tb += (seg + TILE_E - 1) / TILE_E;
        }
        base[RELS] = tb;
        g_ticket = 0;                               // re-zero for next replay
    }
    __syncthreads();
    int total = base[RELS];
    for (int t = threadIdx.x; t < MAX_TILES; t += 256) {
        if (t >= total) { g_tileCnt[t] = 0; continue; }
        int r = 0;
        while (t >= base[r + 1]) r++;
        int i2 = t - base[r];
        int off = g_relStart[r] + i2 * TILE_E;
        int c = g_relStart[r + 1] - off;
        if (c > TILE_E) c = TILE_E;
        g_tileRel[t] = r;
        g_tileOff[t] = off;
        g_tileCnt[t] = c;
    }
}

// ---------------- launch 2: stable-ish counting-sort scatter ----------------
__global__ void __launch_bounds__(256) k_scatter(const int* __restrict__ etype) {
    __shared__ int scur[RELS];
    __shared__ int sbase[RELS];
    if (threadIdx.x < RELS) scur[threadIdx.x] = 0;
    __syncthreads();
    int e = blockIdx.x * blockDim.x + threadIdx.x;
    int r = 0, lp = 0;
    bool ok = (e < E_EDGES);
    if (ok) {
        r = etype[e];
        lp = atomicAdd(&scur[r], 1);
    }
    __syncthreads();
    if (threadIdx.x < RELS)
        sbase[threadIdx.x] = atomicAdd(&g_cursor[threadIdx.x], scur[threadIdx.x]);
    __syncthreads();
    if (ok) g_perm[g_relStart[r] + sbase[r] + lp] = e;
}

// ---------------- relu + split between layers ----------------
__global__ void __launch_bounds__(256) k_relusplit() {
    int idx = blockIdx.x * 256 + threadIdx.x;       // < N*D exactly
    int node = idx >> 7, k = idx & 127;
    float v = fmaxf(g_buf[idx], 0.f);
    __nv_bfloat16 h, l;
    splitf(v, h, l);
    g_hs1[(size_t)node * 256 + k]       = h;
    g_hs1[(size_t)node * 256 + 128 + k] = l;
}

// ---------------- mma helpers ----------------
__device__ __forceinline__ void mma16816(float* c, uint32_t a0, uint32_t a1,
                                         uint32_t a2, uint32_t a3,
                                         uint32_t b0, uint32_t b1) {
    asm volatile(
        "mma.sync.aligned.m16n8k16.row.col.f32.bf16.bf16.f32 "
        "{%0,%1,%2,%3}, {%4,%5,%6,%7}, {%8,%9}, {%0,%1,%2,%3};"
        : "+f"(c[0]), "+f"(c[1]), "+f"(c[2]), "+f"(c[3])
        : "r"(a0), "r"(a1), "r"(a2), "r"(a3), "r"(b0), "r"(b1));
}

__device__ __forceinline__ void red_v4(float* ptr, float x, float y, float z, float w) {
    asm volatile("red.global.add.v4.f32 [%0], {%1,%2,%3,%4};"
                 :: "l"(ptr), "f"(x), "f"(y), "f"(z), "f"(w) : "memory");
}

// ---------------- fused GEMM kernel ----------------
// ROOTMODE=1: out[rowBase+e] = hs[rowBase+e] @ W + bias   (coalesced store)
// ROOTMODE=0: out[dst[e]]   += (hs[src[e]] @ W[rel]) * invc[rel,dst]  (red.v4)
// hs rows are pre-split bf16: [0:128)=hi, [128:256)=lo per node.
template<int ROOTMODE>
__global__ void __launch_bounds__(512, 1)
k_mma(const __nv_bfloat16* __restrict__ hs,
      const __nv_bfloat16* __restrict__ Whi,
      const __nv_bfloat16* __restrict__ Wlo,
      const float* __restrict__ bias,
      const int* __restrict__ src,
      const int* __restrict__ dst,
      float* __restrict__ out) {
    extern __shared__ uint32_t sm[];
    uint32_t* sAhi = sm + SM_AHI;
    uint32_t* sAlo = sm + SM_ALO;
    uint32_t* sWhi = sm + SM_WHI;
    uint32_t* sWlo = sm + SM_WLO;
    int*   sDst  = (int*)(sm + SM_DST);
    float* sInv  = (float*)(sm + SM_INV);
    float* sBias = (float*)(sm + SM_BIAS);
    int*   sSrc  = (int*)(sm + SM_SRC);
    float* sOut  = (float*)(sm + SM_AHI);   // reused after MMA phase

    int t = blockIdx.x;
    int cnt, r = 0, off = 0, rowBase = 0;
    if (ROOTMODE) {
        rowBase = t * TILE_E;
        cnt = N_NODES - rowBase;
        if (cnt > TILE_E) cnt = TILE_E;
    } else {
        cnt = g_tileCnt[t];
        if (cnt == 0) return;
        r = g_tileRel[t];
        off = g_tileOff[t];
    }

    const __nv_bfloat16* gwh = Whi + (size_t)r * (D * D);
    const __nv_bfloat16* gwl = Wlo + (size_t)r * (D * D);

    // ---- W staging (hi+lo), [n][k] rows of 128 bf16 -> smem stride 68 words
    for (int i = threadIdx.x; i < 128 * 16; i += 512) {
        int n = i >> 4, q = i & 15;
        *(uint4*)&sWhi[n * 68 + q * 4] = *(const uint4*)(gwh + n * 128 + q * 8);
        *(uint4*)&sWlo[n * 68 + q * 4] = *(const uint4*)(gwl + n * 128 + q * 8);
    }
    // ---- indices / bias
    if (threadIdx.x < TILE_E) {
        int i = threadIdx.x;
        if (ROOTMODE) {
            sBias[i] = bias[i];
        } else {
            if (i < cnt) {
                int e = g_perm[off + i];
                sSrc[i] = src[e];
                int d = dst[e];
                sDst[i] = d;
                sInv[i] = g_invc[(size_t)r * N_NODES + d];
            } else {
                sSrc[i] = 0; sDst[i] = 0; sInv[i] = 0.f;
            }
        }
    }
    __syncthreads();

    // ---- A staging: pure bf16 copies (512B contiguous per row: hi|lo)
    for (int i = threadIdx.x; i < 128 * 32; i += 512) {
        int e = i >> 5, q = i & 31;                 // q: uint4 index within 512B row
        uint4 v = make_uint4(0, 0, 0, 0);
        if (e < cnt) {
            const uint4* rp = (const uint4*)(hs + (ROOTMODE ? (size_t)(rowBase + e)
                                                            : (size_t)sSrc[e]) * 256);
            v = rp[q];
        }
        int arr = q >> 4, qq = q & 15;
        uint32_t* dp = (arr ? sAlo : sAhi) + e * 68 + qq * 4;
        *(uint4*)dp = v;
    }
    __syncthreads();

    // ---- MMA phase: 16 warps = 8 m-tiles (16 rows) x 2 n-halves (64 cols)
    int lane = threadIdx.x & 31;
    int wid  = threadIdx.x >> 5;
    int g    = lane >> 2;     // 0..7
    int tig  = lane & 3;      // 0..3
    int mtile = wid & 7;
    int nhalf = wid >> 3;
    int m0 = mtile * 16;

    float acc[8][4];
#pragma unroll
    for (int j = 0; j < 8; j++)
#pragma unroll
        for (int c = 0; c < 4; c++) acc[j][c] = 0.f;

    int aBase = (m0 + g) * 68 + tig;
    int bBase = (nhalf * 64 + g) * 68 + tig;

#pragma unroll
    for (int kc = 0; kc < 8; kc++) {
        int ko = kc * 8;
        uint32_t ah0 = sAhi[aBase + ko];
        uint32_t ah1 = sAhi[aBase + 544 + ko];
        uint32_t ah2 = sAhi[aBase + ko + 4];
        uint32_t ah3 = sAhi[aBase + 544 + ko + 4];
        uint32_t al0 = sAlo[aBase + ko];
        uint32_t al1 = sAlo[aBase + 544 + ko];
        uint32_t al2 = sAlo[aBase + ko + 4];
        uint32_t al3 = sAlo[aBase + 544 + ko + 4];
#pragma unroll
        for (int j = 0; j < 8; j++) {
            int bo = bBase + j * 544 + ko;
            uint32_t bh0 = sWhi[bo], bh1 = sWhi[bo + 4];
            uint32_t bl0 = sWlo[bo], bl1 = sWlo[bo + 4];
            mma16816(acc[j], al0, al1, al2, al3, bh0, bh1);  // lo*hi
            mma16816(acc[j], ah0, ah1, ah2, ah3, bl0, bl1);  // hi*lo
            mma16816(acc[j], ah0, ah1, ah2, ah3, bh0, bh1);  // hi*hi
        }
    }

    // ---- epilogue: bounce through smem, then coalesced v4 stores / reductions
    __syncthreads();   // all smem A reads done; safe to reuse region as sOut

    int colb = nhalf * 64 + tig * 2;
    int lr0 = m0 + g, lr1 = lr0 + 8;
#pragma unroll
    for (int j = 0; j < 8; j++) {
        int col = colb + j * 8;
        sOut[lr0 * OSTR + col]     = acc[j][0];
        sOut[lr0 * OSTR + col + 1] = acc[j][1];
        sOut[lr1 * OSTR + col]     = acc[j][2];
        sOut[lr1 * OSTR + col + 1] = acc[j][3];
    }
    __syncthreads();

    if (ROOTMODE) {
        for (int i = threadIdx.x; i < 128 * 32; i += 512) {
            int e = i >> 5, q = i & 31;
            int row = rowBase + e;
            if (row < N_NODES) {
                float4 v = *(const float4*)&sOut[e * OSTR + q * 4];
                v.x += sBias[q * 4];
                v.y += sBias[q * 4 + 1];
                v.z += sBias[q * 4 + 2];
                v.w += sBias[q * 4 + 3];
                *(float4*)(out + (size_t)row * D + q * 4) = v;
            }
        }
    } else {
        for (int i = threadIdx.x; i < 128 * 32; i += 512) {
            int e = i >> 5, q = i & 31;
            if (e < cnt) {
                float inv = sInv[e];
                float4 v = *(const float4*)&sOut[e * OSTR + q * 4];
                float* op = out + (size_t)sDst[e] * D + q * 4;
                red_v4(op, v.x * inv, v.y * inv, v.z * inv, v.w * inv);
            }
        }
    }
}

// ---------------- launch ----------------
extern "C" void kernel_launch(void* const* d_in, const int* in_sizes, int n_in,
                              void* d_out, int out_size) {
    const int*   x     = (const int*)d_in[0];
    const int*   edge  = (const int*)d_in[1];   // [2,E]: src row then dst row
    const int*   etype = (const int*)d_in[2];
    const float* emb   = (const float*)d_in[3];
    const float* w1    = (const float*)d_in[4];
    const float* root1 = (const float*)d_in[5];
    const float* b1    = (const float*)d_in[6];
    const float* w2    = (const float*)d_in[7];
    const float* root2 = (const float*)d_in[8];
    const float* b2    = (const float*)d_in[9];
    float* out = (float*)d_out;

    const int* src  = edge;
    const int* dstp = edge + E_EDGES;

    cudaFuncSetAttribute(k_mma<0>, cudaFuncAttributeMaxDynamicSharedMemorySize, SMEM_BYTES);
    cudaFuncSetAttribute(k_mma<1>, cudaFuncAttributeMaxDynamicSharedMemorySize, SMEM_BYTES);

    float *buf;
    __nv_bfloat16 *hs0, *hs1;
    __nv_bfloat16 *w1hi, *w1lo, *w2hi, *w2lo, *r1hi, *r1lo, *r2hi, *r2lo;
    {
        void* p;
        cudaGetSymbolAddress(&p, g_buf);  buf = (float*)p;
        cudaGetSymbolAddress(&p, g_hs0);  hs0 = (__nv_bfloat16*)p;
        cudaGetSymbolAddress(&p, g_hs1);  hs1 = (__nv_bfloat16*)p;
        cudaGetSymbolAddress(&p, g_w1hi); w1hi = (__nv_bfloat16*)p;
        cudaGetSymbolAddress(&p, g_w1lo); w1lo = (__nv_bfloat16*)p;
        cudaGetSymbolAddress(&p, g_w2hi); w2hi = (__nv_bfloat16*)p;
        cudaGetSymbolAddress(&p, g_w2lo); w2lo = (__nv_bfloat16*)p;
        cudaGetSymbolAddress(&p, g_r1hi); r1hi = (__nv_bfloat16*)p;
        cudaGetSymbolAddress(&p, g_r1lo); r1lo = (__nv_bfloat16*)p;
        cudaGetSymbolAddress(&p, g_r2hi); r2hi = (__nv_bfloat16*)p;
        cudaGetSymbolAddress(&p, g_r2lo); r2lo = (__nv_bfloat16*)p;
    }

    // 0: fused preprocessing (count+hist | gather-split emb | weight splits)
    k_mega<<<MEGA_BLOCKS, 256>>>(x, emb, etype, dstp, w1, w2, root1, root2);
    // 1: inverse degrees + (last block) scan + tile table
    k_inv_scan<<<(RELS * N_NODES + 255) / 256, 256>>>();
    // 2: relation-sorted permutation
    k_scatter<<<(E_EDGES + 255) / 256, 256>>>(etype);
    // 3: layer-1 root GEMM (PROFILED SLOT) — buf = hs0 @ root1 + b1
    k_mma<1><<<ROOT_TILES, 512, SMEM_BYTES>>>(hs0, r1hi, r1lo, b1, src, dstp, buf);
    // 4: layer-1 edge messages — buf += (hs0[src] @ w1[rel]) * invc
    k_mma<0><<<MAX_TILES, 512, SMEM_BYTES>>>(hs0, w1hi, w1lo, b1, src, dstp, buf);
    // 5: relu + split for layer 2
    k_relusplit<<<GB, 256>>>();
    // 6: layer-2 root GEMM — out = hs1 @ root2 + b2
    k_mma<1><<<ROOT_TILES, 512, SMEM_BYTES>>>(hs1, r2hi, r2lo, b2, src, dstp, out);
    // 7: layer-2 edge messages — out += (hs1[src] @ w2[rel]) * invc
    k_mma<0><<<MAX_TILES, 512, SMEM_BYTES>>>(hs1, w2hi, w2lo, b2, src, dstp, out);
}

// round 15
// speedup vs baseline: 1.0107x; 1.0107x over previous
#include <cuda_runtime.h>
#include <cuda_bf16.h>
#include <cstdint>

// ---------------- problem constants ----------------
#define N_NODES   100000
#define E_EDGES   600000
#define RELS      20
#define D         128
#define TILE_E    128
#define MAX_TILES ((E_EDGES + TILE_E - 1) / TILE_E + RELS)   // 4708
#define ROOT_TILES ((N_NODES + TILE_E - 1) / TILE_E)          // 782

// smem word layout (uint32 words), stride 68 words per row (136 bf16)
#define SM_AHI    0
#define SM_ALO    8704
#define SM_WHI    17408
#define SM_WLO    26112
#define SM_DST    34816
#define SM_INV    34944
#define SM_BIAS   35072
#define SM_SRC    35200
#define SMEM_WORDS 35328
#define SMEM_BYTES (SMEM_WORDS * 4)  // 141312
#define OSTR      132                // output bounce stride (fp32 words)

// mega-kernel block ranges
#define CB  2344     // count: ceil(E/256)
#define GB  50000    // gather+split emb: N*D/256
#define WB  1280     // wsplit per W tensor: 20*16384/256
#define RB  64       // wsplit per root tensor: 16384/256
#define MEGA_BLOCKS (CB + GB + 2*WB + 2*RB)   // 55032

// ---------------- device scratch ----------------
// activations stored pre-split: per node 256 bf16 = [0:128) hi | [128:256) lo
__device__ __nv_bfloat16 g_hs0[(size_t)N_NODES * 256];  // layer-1 input
__device__ float         g_buf[(size_t)N_NODES * D];    // layer-1 fp32 accumulator
__device__ __nv_bfloat16 g_hs1[(size_t)N_NODES * 256];  // relu(buf) split
__device__ float g_invc[(size_t)RELS * N_NODES];
__device__ int   g_cnt [(size_t)RELS * N_NODES];
__device__ int   g_hist[RELS];
__device__ int   g_relStart[RELS + 1];
__device__ int   g_cursor[RELS];
__device__ unsigned g_ticket;
__device__ int   g_perm[E_EDGES];
__device__ int   g_tileRel[MAX_TILES];
__device__ int   g_tileOff[MAX_TILES];
__device__ int   g_tileCnt[MAX_TILES];

// split-bf16 weights, transposed to [n][k] for col-major B fragments
__device__ __nv_bfloat16 g_w1hi[(size_t)RELS * D * D];
__device__ __nv_bfloat16 g_w1lo[(size_t)RELS * D * D];
__device__ __nv_bfloat16 g_w2hi[(size_t)RELS * D * D];
__device__ __nv_bfloat16 g_w2lo[(size_t)RELS * D * D];
__device__ __nv_bfloat16 g_r1hi[D * D];
__device__ __nv_bfloat16 g_r1lo[D * D];
__device__ __nv_bfloat16 g_r2hi[D * D];
__device__ __nv_bfloat16 g_r2lo[D * D];

// ---------------- helpers ----------------
__device__ __forceinline__ void splitf(float v, __nv_bfloat16& h, __nv_bfloat16& l) {
    h = __float2bfloat16_rn(v);
    l = __float2bfloat16_rn(v - __bfloat162float(h));
}

__device__ __forceinline__ void wsplit_one(const float* __restrict__ w,
                                           __nv_bfloat16* __restrict__ hi,
                                           __nv_bfloat16* __restrict__ lo, int idx) {
    int m = idx >> 14;
    int rem = idx & 16383;
    int k = rem >> 7;
    int n = rem & 127;
    float v = w[(size_t)m * 16384 + k * 128 + n];
    __nv_bfloat16 h, l;
    splitf(v, h, l);
    size_t dst = (size_t)m * 16384 + n * 128 + k;
    hi[dst] = h;
    lo[dst] = l;
}

// ---------------- launch 0: mega preprocessing ----------------
__global__ void __launch_bounds__(256) k_mega(const int* __restrict__ x,
                                              const float* __restrict__ emb,
                                              const int* __restrict__ etype,
                                              const int* __restrict__ dst,
                                              const float* __restrict__ w1,
                                              const float* __restrict__ w2,
                                              const float* __restrict__ r1,
                                              const float* __restrict__ r2) {
    __shared__ int sh[RELS];
    int b = blockIdx.x;
    if (b < CB) {
        // per-(rel,dst) counts + per-rel histogram
        if (threadIdx.x < RELS) sh[threadIdx.x] = 0;
        __syncthreads();
        int e = b * 256 + threadIdx.x;
        if (e < E_EDGES) {
            int r = etype[e];
            atomicAdd(&g_cnt[(size_t)r * N_NODES + dst[e]], 1);
            atomicAdd(&sh[r], 1);
        }
        __syncthreads();
        if (threadIdx.x < RELS) atomicAdd(&g_hist[threadIdx.x], sh[threadIdx.x]);
    } else if (b < CB + GB) {
        // gather emb by x, split to bf16 hi/lo
        int idx = (b - CB) * 256 + threadIdx.x;     // < N*D exactly
        int node = idx >> 7, k = idx & 127;
        float v = emb[(size_t)x[node] * D + k];
        __nv_bfloat16 h, l;
        splitf(v, h, l);
        g_hs0[(size_t)node * 256 + k]       = h;
        g_hs0[(size_t)node * 256 + 128 + k] = l;
    } else if (b < CB + GB + WB) {
        wsplit_one(w1, g_w1hi, g_w1lo, (b - CB - GB) * 256 + threadIdx.x);
    } else if (b < CB + GB + 2 * WB) {
        wsplit_one(w2, g_w2hi, g_w2lo, (b - CB - GB - WB) * 256 + threadIdx.x);
    } else if (b < CB + GB + 2 * WB + RB) {
        wsplit_one(r1, g_r1hi, g_r1lo, (b - CB - GB - 2 * WB) * 256 + threadIdx.x);
    } else {
        wsplit_one(r2, g_r2hi, g_r2lo, (b - CB - GB - 2 * WB - RB) * 256 + threadIdx.x);
    }
}

// ---------------- launch 1: invc + (last block) scan + tile table ----------------
__global__ void __launch_bounds__(256) k_inv_scan() {
    __shared__ bool isLast;
    int i = blockIdx.x * 256 + threadIdx.x;
    if (i < RELS * N_NODES) {
        int c = g_cnt[i];
        g_invc[i] = 1.0f / (float)(c > 1 ? c : 1);
        g_cnt[i] = 0;                               // re-zero for next replay
    }
    __threadfence();
    if (threadIdx.x == 0) {
        unsigned t = atomicAdd(&g_ticket, 1u);
        isLast = (t == gridDim.x - 1);
    }
    __syncthreads();
    if (!isLast) return;

    __shared__ int base[RELS + 1];
    if (threadIdx.x == 0) {
        int bsum = 0;
        for (int r = 0; r < RELS; r++) {
            g_relStart[r] = bsum;
            bsum += g_hist[r];
            g_cursor[r] = 0;
            g_hist[r] = 0;                          // re-zero for next replay
        }
        g_relStart[RELS] = bsum;
        int tb = 0;
        for (int r = 0; r < RELS; r++) {
            base[r] = tb;
            int seg = g_relStart[r + 1] - g_relStart[r];
            tb += (seg + TILE_E - 1) / TILE_E;
        }
        base[RELS] = tb;
        g_ticket = 0;                               // re-zero for next replay
    }
    __syncthreads();
    int total = base[RELS];
    for (int t = threadIdx.x; t < MAX_TILES; t += 256) {
        if (t >= total) { g_tileCnt[t] = 0; continue; }
        int r = 0;
        while (t >= base[r + 1]) r++;
        int i2 = t - base[r];
        int off = g_relStart[r] + i2 * TILE_E;
        int c = g_relStart[r + 1] - off;
        if (c > TILE_E) c = TILE_E;
        g_tileRel[t] = r;
        g_tileOff[t] = off;
        g_tileCnt[t] = c;
    }
}

// ---------------- launch 2: stable-ish counting-sort scatter ----------------
__global__ void __launch_bounds__(256) k_scatter(const int* __restrict__ etype) {
    __shared__ int scur[RELS];
    __shared__ int sbase[RELS];
    if (threadIdx.x < RELS) scur[threadIdx.x] = 0;
    __syncthreads();
    int e = blockIdx.x * blockDim.x + threadIdx.x;
    int r = 0, lp = 0;
    bool ok = (e < E_EDGES);
    if (ok) {
        r = etype[e];
        lp = atomicAdd(&scur[r], 1);
    }
    __syncthreads();
    if (threadIdx.x < RELS)
        sbase[threadIdx.x] = atomicAdd(&g_cursor[threadIdx.x], scur[threadIdx.x]);
    __syncthreads();
    if (ok) g_perm[g_relStart[r] + sbase[r] + lp] = e;
}

// ---------------- relu + split between layers ----------------
__global__ void __launch_bounds__(256) k_relusplit() {
    int idx = blockIdx.x * 256 + threadIdx.x;       // < N*D exactly
    int node = idx >> 7, k = idx & 127;
    float v = fmaxf(g_buf[idx], 0.f);
    __nv_bfloat16 h, l;
    splitf(v, h, l);
    g_hs1[(size_t)node * 256 + k]       = h;
    g_hs1[(size_t)node * 256 + 128 + k] = l;
}

// ---------------- mma helpers ----------------
__device__ __forceinline__ void mma16816(float* c, uint32_t a0, uint32_t a1,
                                         uint32_t a2, uint32_t a3,
                                         uint32_t b0, uint32_t b1) {
    asm volatile(
        "mma.sync.aligned.m16n8k16.row.col.f32.bf16.bf16.f32 "
        "{%0,%1,%2,%3}, {%4,%5,%6,%7}, {%8,%9}, {%0,%1,%2,%3};"
        : "+f"(c[0]), "+f"(c[1]), "+f"(c[2]), "+f"(c[3])
        : "r"(a0), "r"(a1), "r"(a2), "r"(a3), "r"(b0), "r"(b1));
}

__device__ __forceinline__ void red_v4(float* ptr, float x, float y, float z, float w) {
    asm volatile("red.global.add.v4.f32 [%0], {%1,%2,%3,%4};"
                 :: "l"(ptr), "f"(x), "f"(y), "f"(z), "f"(w) : "memory");
}

// ---------------- fused GEMM kernel ----------------
// ROOTMODE=1: out[rowBase+e] = hs[rowBase+e] @ W + bias   (coalesced store)
// ROOTMODE=0: out[dst[e]]   += (hs[src[e]] @ W[rel]) * invc[rel,dst]  (red.v4)
// hs rows are pre-split bf16: [0:128)=hi, [128:256)=lo per node.
template<int ROOTMODE>
__global__ void __launch_bounds__(512, 1)
k_mma(const __nv_bfloat16* __restrict__ hs,
      const __nv_bfloat16* __restrict__ Whi,
      const __nv_bfloat16* __restrict__ Wlo,
      const float* __restrict__ bias,
      const int* __restrict__ src,
      const int* __restrict__ dst,
      float* __restrict__ out) {
    extern __shared__ uint32_t sm[];
    uint32_t* sAhi = sm + SM_AHI;
    uint32_t* sAlo = sm + SM_ALO;
    uint32_t* sWhi = sm + SM_WHI;
    uint32_t* sWlo = sm + SM_WLO;
    int*   sDst  = (int*)(sm + SM_DST);
    float* sInv  = (float*)(sm + SM_INV);
    float* sBias = (float*)(sm + SM_BIAS);
    int*   sSrc  = (int*)(sm + SM_SRC);
    float* sOut  = (float*)(sm + SM_AHI);   // reused after MMA phase

    int t = blockIdx.x;
    int cnt, r = 0, off = 0, rowBase = 0;
    if (ROOTMODE) {
        rowBase = t * TILE_E;
        cnt = N_NODES - rowBase;
        if (cnt > TILE_E) cnt = TILE_E;
    } else {
        cnt = g_tileCnt[t];
        if (cnt == 0) return;
        r = g_tileRel[t];
        off = g_tileOff[t];
    }

    const __nv_bfloat16* gwh = Whi + (size_t)r * (D * D);
    const __nv_bfloat16* gwl = Wlo + (size_t)r * (D * D);

    // ---- W staging (hi+lo), [n][k] rows of 128 bf16 -> smem stride 68 words
    for (int i = threadIdx.x; i < 128 * 16; i += 512) {
        int n = i >> 4, q = i & 15;
        *(uint4*)&sWhi[n * 68 + q * 4] = *(const uint4*)(gwh + n * 128 + q * 8);
        *(uint4*)&sWlo[n * 68 + q * 4] = *(const uint4*)(gwl + n * 128 + q * 8);
    }
    // ---- indices / bias
    if (threadIdx.x < TILE_E) {
        int i = threadIdx.x;
        if (ROOTMODE) {
            sBias[i] = bias[i];
        } else {
            if (i < cnt) {
                int e = g_perm[off + i];
                sSrc[i] = src[e];
                int d = dst[e];
                sDst[i] = d;
                sInv[i] = g_invc[(size_t)r * N_NODES + d];
            } else {
                sSrc[i] = 0; sDst[i] = 0; sInv[i] = 0.f;
            }
        }
    }
    __syncthreads();

    // ---- A staging: pure bf16 copies (512B contiguous per row: hi|lo)
    for (int i = threadIdx.x; i < 128 * 32; i += 512) {
        int e = i >> 5, q = i & 31;                 // q: uint4 index within 512B row
        uint4 v = make_uint4(0, 0, 0, 0);
        if (e < cnt) {
            const uint4* rp = (const uint4*)(hs + (ROOTMODE ? (size_t)(rowBase + e)
                                                            : (size_t)sSrc[e]) * 256);
            v = rp[q];
        }
        int arr = q >> 4, qq = q & 15;
        uint32_t* dp = (arr ? sAlo : sAhi) + e * 68 + qq * 4;
        *(uint4*)dp = v;
    }
    __syncthreads();

    // ---- MMA phase: 16 warps = 8 m-tiles (16 rows) x 2 n-halves (64 cols)
    int lane = threadIdx.x & 31;
    int wid  = threadIdx.x >> 5;
    int g    = lane >> 2;     // 0..7
    int tig  = lane & 3;      // 0..3
    int mtile = wid & 7;
    int nhalf = wid >> 3;
    int m0 = mtile * 16;

    float acc[8][4];
#pragma unroll
    for (int j = 0; j < 8; j++)
#pragma unroll
        for (int c = 0; c < 4; c++) acc[j][c] = 0.f;

    int aBase = (m0 + g) * 68 + tig;
    int bBase = (nhalf * 64 + g) * 68 + tig;

#pragma unroll
    for (int kc = 0; kc < 8; kc++) {
        int ko = kc * 8;
        uint32_t ah0 = sAhi[aBase + ko];
        uint32_t ah1 = sAhi[aBase + 544 + ko];
        uint32_t ah2 = sAhi[aBase + ko + 4];
        uint32_t ah3 = sAhi[aBase + 544 + ko + 4];
        uint32_t al0 = sAlo[aBase + ko];
        uint32_t al1 = sAlo[aBase + 544 + ko];
        uint32_t al2 = sAlo[aBase + ko + 4];
        uint32_t al3 = sAlo[aBase + 544 + ko + 4];
#pragma unroll
        for (int j = 0; j < 8; j++) {
            int bo = bBase + j * 544 + ko;
            uint32_t bh0 = sWhi[bo], bh1 = sWhi[bo + 4];
            uint32_t bl0 = sWlo[bo], bl1 = sWlo[bo + 4];
            mma16816(acc[j], al0, al1, al2, al3, bh0, bh1);  // lo*hi
            mma16816(acc[j], ah0, ah1, ah2, ah3, bl0, bl1);  // hi*lo
            mma16816(acc[j], ah0, ah1, ah2, ah3, bh0, bh1);  // hi*hi
        }
    }

    // ---- epilogue: bounce through smem, then coalesced v4 stores / reductions
    __syncthreads();   // all smem A reads done; safe to reuse region as sOut

    int colb = nhalf * 64 + tig * 2;
    int lr0 = m0 + g, lr1 = lr0 + 8;
#pragma unroll
    for (int j = 0; j < 8; j++) {
        int col = colb + j * 8;
        sOut[lr0 * OSTR + col]     = acc[j][0];
        sOut[lr0 * OSTR + col + 1] = acc[j][1];
        sOut[lr1 * OSTR + col]     = acc[j][2];
        sOut[lr1 * OSTR + col + 1] = acc[j][3];
    }
    __syncthreads();

    if (ROOTMODE) {
        for (int i = threadIdx.x; i < 128 * 32; i += 512) {
            int e = i >> 5, q = i & 31;
            int row = rowBase + e;
            if (row < N_NODES) {
                float4 v = *(const float4*)&sOut[e * OSTR + q * 4];
                v.x += sBias[q * 4];
                v.y += sBias[q * 4 + 1];
                v.z += sBias[q * 4 + 2];
                v.w += sBias[q * 4 + 3];
                *(float4*)(out + (size_t)row * D + q * 4) = v;
            }
        }
    } else {
        for (int i = threadIdx.x; i < 128 * 32; i += 512) {
            int e = i >> 5, q = i & 31;
            if (e < cnt) {
                float inv = sInv[e];
                float4 v = *(const float4*)&sOut[e * OSTR + q * 4];
                float* op = out + (size_t)sDst[e] * D + q * 4;
                red_v4(op, v.x * inv, v.y * inv, v.z * inv, v.w * inv);
            }
        }
    }
}

// ---------------- launch ----------------
extern "C" void kernel_launch(void* const* d_in, const int* in_sizes, int n_in,
                              void* d_out, int out_size) {
    const int*   x     = (const int*)d_in[0];
    const int*   edge  = (const int*)d_in[1];   // [2,E]: src row then dst row
    const int*   etype = (const int*)d_in[2];
    const float* emb   = (const float*)d_in[3];
    const float* w1    = (const float*)d_in[4];
    const float* root1 = (const float*)d_in[5];
    const float* b1    = (const float*)d_in[6];
    const float* w2    = (const float*)d_in[7];
    const float* root2 = (const float*)d_in[8];
    const float* b2    = (const float*)d_in[9];
    float* out = (float*)d_out;

    const int* src  = edge;
    const int* dstp = edge + E_EDGES;

    cudaFuncSetAttribute(k_mma<0>, cudaFuncAttributeMaxDynamicSharedMemorySize, SMEM_BYTES);
    cudaFuncSetAttribute(k_mma<1>, cudaFuncAttributeMaxDynamicSharedMemorySize, SMEM_BYTES);

    float *buf;
    __nv_bfloat16 *hs0, *hs1;
    __nv_bfloat16 *w1hi, *w1lo, *w2hi, *w2lo, *r1hi, *r1lo, *r2hi, *r2lo;
    {
        void* p;
        cudaGetSymbolAddress(&p, g_buf);  buf = (float*)p;
        cudaGetSymbolAddress(&p, g_hs0);  hs0 = (__nv_bfloat16*)p;
        cudaGetSymbolAddress(&p, g_hs1);  hs1 = (__nv_bfloat16*)p;
        cudaGetSymbolAddress(&p, g_w1hi); w1hi = (__nv_bfloat16*)p;
        cudaGetSymbolAddress(&p, g_w1lo); w1lo = (__nv_bfloat16*)p;
        cudaGetSymbolAddress(&p, g_w2hi); w2hi = (__nv_bfloat16*)p;
        cudaGetSymbolAddress(&p, g_w2lo); w2lo = (__nv_bfloat16*)p;
        cudaGetSymbolAddress(&p, g_r1hi); r1hi = (__nv_bfloat16*)p;
        cudaGetSymbolAddress(&p, g_r1lo); r1lo = (__nv_bfloat16*)p;
        cudaGetSymbolAddress(&p, g_r2hi); r2hi = (__nv_bfloat16*)p;
        cudaGetSymbolAddress(&p, g_r2lo); r2lo = (__nv_bfloat16*)p;
    }

    // 0: fused preprocessing (count+hist | gather-split emb | weight splits)
    k_mega<<<MEGA_BLOCKS, 256>>>(x, emb, etype, dstp, w1, w2, root1, root2);
    // 1: inverse degrees + (last block) scan + tile table
    k_inv_scan<<<(RELS * N_NODES + 255) / 256, 256>>>();
    // 2: relation-sorted permutation
    k_scatter<<<(E_EDGES + 255) / 256, 256>>>(etype);
    // 3: layer-1 root GEMM (PROFILED SLOT) — buf = hs0 @ root1 + b1
    k_mma<1><<<ROOT_TILES, 512, SMEM_BYTES>>>(hs0, r1hi, r1lo, b1, src, dstp, buf);
    // 4: layer-1 edge messages — buf += (hs0[src] @ w1[rel]) * invc
    k_mma<0><<<MAX_TILES, 512, SMEM_BYTES>>>(hs0, w1hi, w1lo, b1, src, dstp, buf);
    // 5: relu + split for layer 2
    k_relusplit<<<GB, 256>>>();
    // 6: layer-2 root GEMM — out = hs1 @ root2 + b2
    k_mma<1><<<ROOT_TILES, 512, SMEM_BYTES>>>(hs1, r2hi, r2lo, b2, src, dstp, out);
    // 7: layer-2 edge messages — out += (hs1[src] @ w2[rel]) * invc
    k_mma<0><<<MAX_TILES, 512, SMEM_BYTES>>>(hs1, w2hi, w2lo, b2, src, dstp, out);
}

// round 16
// speedup vs baseline: 1.0526x; 1.0414x over previous
#include <cuda_runtime.h>
#include <cuda_bf16.h>
#include <cstdint>

// ---------------- problem constants ----------------
#define N_NODES   100000
#define E_EDGES   600000
#define RELS      20
#define D         128
#define TILE_E    64
#define MAX_TILES ((E_EDGES + TILE_E - 1) / TILE_E + RELS)    // 9395
#define ROOT_TILES ((N_NODES + TILE_E - 1) / TILE_E)           // 1563

// smem word layout (uint32 words); A/W rows of 128 bf16 = 64 words, stride 68
#define SM_AHI    0            // 64 rows * 68 = 4352
#define SM_ALO    4352         // 4352
#define SM_WHI    8704         // 128 rows * 68 = 8704
#define SM_WLO    17408        // 8704
#define SM_DST    26112        // 64
#define SM_INV    26176        // 64
#define SM_BIAS   26240        // 128
#define SM_SRC    26368        // 64
#define SMEM_WORDS 26432
#define SMEM_BYTES (SMEM_WORDS * 4)   // 105728 -> 2 CTAs/SM
#define OSTR      132                 // output bounce stride (fp32 words)

// mega-kernel block ranges
#define CB  2344     // count: ceil(E/256)
#define GB  50000    // gather+split emb: N*D/256
#define WB  1280     // wsplit per W tensor: 20*16384/256
#define RB  64       // wsplit per root tensor: 16384/256
#define MEGA_BLOCKS (CB + GB + 2*WB + 2*RB)   // 55032

// ---------------- device scratch ----------------
// activations pre-split: per node 256 bf16 = [0:128) hi | [128:256) lo
__device__ __nv_bfloat16 g_hs0[(size_t)N_NODES * 256];
__device__ float         g_buf[(size_t)N_NODES * D];
__device__ __nv_bfloat16 g_hs1[(size_t)N_NODES * 256];
__device__ float g_invc[(size_t)RELS * N_NODES];
__device__ int   g_cnt [(size_t)RELS * N_NODES];
__device__ int   g_hist[RELS];
__device__ int   g_relStart[RELS + 1];
__device__ int   g_cursor[RELS];
__device__ unsigned g_ticket;
__device__ int   g_perm[E_EDGES];
__device__ int   g_tileRel[MAX_TILES];
__device__ int   g_tileOff[MAX_TILES];
__device__ int   g_tileCnt[MAX_TILES];

// split-bf16 weights, transposed to [n][k]
__device__ __nv_bfloat16 g_w1hi[(size_t)RELS * D * D];
__device__ __nv_bfloat16 g_w1lo[(size_t)RELS * D * D];
__device__ __nv_bfloat16 g_w2hi[(size_t)RELS * D * D];
__device__ __nv_bfloat16 g_w2lo[(size_t)RELS * D * D];
__device__ __nv_bfloat16 g_r1hi[D * D];
__device__ __nv_bfloat16 g_r1lo[D * D];
__device__ __nv_bfloat16 g_r2hi[D * D];
__device__ __nv_bfloat16 g_r2lo[D * D];

// ---------------- helpers ----------------
__device__ __forceinline__ void splitf(float v, __nv_bfloat16& h, __nv_bfloat16& l) {
    h = __float2bfloat16_rn(v);
    l = __float2bfloat16_rn(v - __bfloat162float(h));
}

__device__ __forceinline__ void wsplit_one(const float* __restrict__ w,
                                           __nv_bfloat16* __restrict__ hi,
                                           __nv_bfloat16* __restrict__ lo, int idx) {
    int m = idx >> 14;
    int rem = idx & 16383;
    int k = rem >> 7;
    int n = rem & 127;
    float v = w[(size_t)m * 16384 + k * 128 + n];
    __nv_bfloat16 h, l;
    splitf(v, h, l);
    size_t dst = (size_t)m * 16384 + n * 128 + k;
    hi[dst] = h;
    lo[dst] = l;
}

// ---------------- launch 0: mega preprocessing ----------------
__global__ void __launch_bounds__(256) k_mega(const int* __restrict__ x,
                                              const float* __restrict__ emb,
                                              const int* __restrict__ etype,
                                              const int* __restrict__ dst,
                                              const float* __restrict__ w1,
                                              const float* __restrict__ w2,
                                              const float* __restrict__ r1,
                                              const float* __restrict__ r2) {
    __shared__ int sh[RELS];
    int b = blockIdx.x;
    if (b < CB) {
        if (threadIdx.x < RELS) sh[threadIdx.x] = 0;
        __syncthreads();
        int e = b * 256 + threadIdx.x;
        if (e < E_EDGES) {
            int r = etype[e];
            atomicAdd(&g_cnt[(size_t)r * N_NODES + dst[e]], 1);
            atomicAdd(&sh[r], 1);
        }
        __syncthreads();
        if (threadIdx.x < RELS) atomicAdd(&g_hist[threadIdx.x], sh[threadIdx.x]);
    } else if (b < CB + GB) {
        int idx = (b - CB) * 256 + threadIdx.x;
        int node = idx >> 7, k = idx & 127;
        float v = emb[(size_t)x[node] * D + k];
        __nv_bfloat16 h, l;
        splitf(v, h, l);
        g_hs0[(size_t)node * 256 + k]       = h;
        g_hs0[(size_t)node * 256 + 128 + k] = l;
    } else if (b < CB + GB + WB) {
        wsplit_one(w1, g_w1hi, g_w1lo, (b - CB - GB) * 256 + threadIdx.x);
    } else if (b < CB + GB + 2 * WB) {
        wsplit_one(w2, g_w2hi, g_w2lo, (b - CB - GB - WB) * 256 + threadIdx.x);
    } else if (b < CB + GB + 2 * WB + RB) {
        wsplit_one(r1, g_r1hi, g_r1lo, (b - CB - GB - 2 * WB) * 256 + threadIdx.x);
    } else {
        wsplit_one(r2, g_r2hi, g_r2lo, (b - CB - GB - 2 * WB - RB) * 256 + threadIdx.x);
    }
}

// ---------------- launch 1: invc + (last block) scan + tile table ----------------
__global__ void __launch_bounds__(256) k_inv_scan() {
    __shared__ bool isLast;
    int i = blockIdx.x * 256 + threadIdx.x;
    if (i < RELS * N_NODES) {
        int c = g_cnt[i];
        g_invc[i] = 1.0f / (float)(c > 1 ? c : 1);
        g_cnt[i] = 0;
    }
    __threadfence();
    if (threadIdx.x == 0) {
        unsigned t = atomicAdd(&g_ticket, 1u);
        isLast = (t == gridDim.x - 1);
    }
    __syncthreads();
    if (!isLast) return;

    __shared__ int base[RELS + 1];
    if (threadIdx.x == 0) {
        int bsum = 0;
        for (int r = 0; r < RELS; r++) {
            g_relStart[r] = bsum;
            bsum += g_hist[r];
            g_cursor[r] = 0;
            g_hist[r] = 0;
        }
        g_relStart[RELS] = bsum;
        int tb = 0;
        for (int r = 0; r < RELS; r++) {
            base[r] = tb;
            int seg = g_relStart[r + 1] - g_relStart[r];
            tb += (seg + TILE_E - 1) / TILE_E;
        }
        base[RELS] = tb;
        g_ticket = 0;
    }
    __syncthreads();
    int total = base[RELS];
    for (int t = threadIdx.x; t < MAX_TILES; t += 256) {
        if (t >= total) { g_tileCnt[t] = 0; continue; }
        int r = 0;
        while (t >= base[r + 1]) r++;
        int i2 = t - base[r];
        int off = g_relStart[r] + i2 * TILE_E;
        int c = g_relStart[r + 1] - off;
        if (c > TILE_E) c = TILE_E;
        g_tileRel[t] = r;
        g_tileOff[t] = off;
        g_tileCnt[t] = c;
    }
}

// ---------------- launch 2: counting-sort scatter ----------------
__global__ void __launch_bounds__(256) k_scatter(const int* __restrict__ etype) {
    __shared__ int scur[RELS];
    __shared__ int sbase[RELS];
    if (threadIdx.x < RELS) scur[threadIdx.x] = 0;
    __syncthreads();
    int e = blockIdx.x * blockDim.x + threadIdx.x;
    int r = 0, lp = 0;
    bool ok = (e < E_EDGES);
    if (ok) {
        r = etype[e];
        lp = atomicAdd(&scur[r], 1);
    }
    __syncthreads();
    if (threadIdx.x < RELS)
        sbase[threadIdx.x] = atomicAdd(&g_cursor[threadIdx.x], scur[threadIdx.x]);
    __syncthreads();
    if (ok) g_perm[g_relStart[r] + sbase[r] + lp] = e;
}

// ---------------- relu + split between layers ----------------
__global__ void __launch_bounds__(256) k_relusplit() {
    int idx = blockIdx.x * 256 + threadIdx.x;
    int node = idx >> 7, k = idx & 127;
    float v = fmaxf(g_buf[idx], 0.f);
    __nv_bfloat16 h, l;
    splitf(v, h, l);
    g_hs1[(size_t)node * 256 + k]       = h;
    g_hs1[(size_t)node * 256 + 128 + k] = l;
}

// ---------------- mma helpers ----------------
__device__ __forceinline__ void mma16816(float* c, uint32_t a0, uint32_t a1,
                                         uint32_t a2, uint32_t a3,
                                         uint32_t b0, uint32_t b1) {
    asm volatile(
        "mma.sync.aligned.m16n8k16.row.col.f32.bf16.bf16.f32 "
        "{%0,%1,%2,%3}, {%4,%5,%6,%7}, {%8,%9}, {%0,%1,%2,%3};"
        : "+f"(c[0]), "+f"(c[1]), "+f"(c[2]), "+f"(c[3])
        : "r"(a0), "r"(a1), "r"(a2), "r"(a3), "r"(b0), "r"(b1));
}

__device__ __forceinline__ void red_v4(float* ptr, float x, float y, float z, float w) {
    asm volatile("red.global.add.v4.f32 [%0], {%1,%2,%3,%4};"
                 :: "l"(ptr), "f"(x), "f"(y), "f"(z), "f"(w) : "memory");
}

// ---------------- fused GEMM kernel ----------------
// 64-edge tiles, 256 threads, ~103KB smem => 2 CTAs/SM for phase overlap.
// ROOTMODE=1: out[rowBase+e] = hs[rowBase+e] @ W + bias
// ROOTMODE=0: out[dst[e]]   += (hs[src[e]] @ W[rel]) * invc[rel,dst]
template<int ROOTMODE>
__global__ void __launch_bounds__(256, 2)
k_mma(const __nv_bfloat16* __restrict__ hs,
      const __nv_bfloat16* __restrict__ Whi,
      const __nv_bfloat16* __restrict__ Wlo,
      const float* __restrict__ bias,
      const int* __restrict__ src,
      const int* __restrict__ dst,
      float* __restrict__ out) {
    extern __shared__ uint32_t sm[];
    uint32_t* sAhi = sm + SM_AHI;
    uint32_t* sAlo = sm + SM_ALO;
    uint32_t* sWhi = sm + SM_WHI;
    uint32_t* sWlo = sm + SM_WLO;
    int*   sDst  = (int*)(sm + SM_DST);
    float* sInv  = (float*)(sm + SM_INV);
    float* sBias = (float*)(sm + SM_BIAS);
    int*   sSrc  = (int*)(sm + SM_SRC);
    float* sOut  = (float*)(sm + SM_AHI);   // reused after MMA (64*OSTR=8448 <= 8704 words)

    int t = blockIdx.x;
    int cnt, r = 0, off = 0, rowBase = 0;
    if (ROOTMODE) {
        rowBase = t * TILE_E;
        cnt = N_NODES - rowBase;
        if (cnt > TILE_E) cnt = TILE_E;
    } else {
        cnt = g_tileCnt[t];
        if (cnt == 0) return;
        r = g_tileRel[t];
        off = g_tileOff[t];
    }

    const __nv_bfloat16* gwh = Whi + (size_t)r * (D * D);
    const __nv_bfloat16* gwl = Wlo + (size_t)r * (D * D);

    // ---- W staging (hi+lo), 128 [n][k] rows -> stride 68 words
    for (int i = threadIdx.x; i < 128 * 16; i += 256) {
        int n = i >> 4, q = i & 15;
        *(uint4*)&sWhi[n * 68 + q * 4] = *(const uint4*)(gwh + n * 128 + q * 8);
        *(uint4*)&sWlo[n * 68 + q * 4] = *(const uint4*)(gwl + n * 128 + q * 8);
    }
    // ---- indices / bias
    if (ROOTMODE) {
        if (threadIdx.x < D) sBias[threadIdx.x] = bias[threadIdx.x];
    } else if (threadIdx.x < TILE_E) {
        int i = threadIdx.x;
        if (i < cnt) {
            int e = g_perm[off + i];
            sSrc[i] = src[e];
            int d = dst[e];
            sDst[i] = d;
            sInv[i] = g_invc[(size_t)r * N_NODES + d];
        } else {
            sSrc[i] = 0; sDst[i] = 0; sInv[i] = 0.f;
        }
    }
    __syncthreads();

    // ---- A staging: pre-split bf16 rows (512B contiguous: hi|lo)
    for (int i = threadIdx.x; i < TILE_E * 32; i += 256) {
        int e = i >> 5, q = i & 31;
        uint4 v = make_uint4(0, 0, 0, 0);
        if (e < cnt) {
            const uint4* rp = (const uint4*)(hs + (ROOTMODE ? (size_t)(rowBase + e)
                                                            : (size_t)sSrc[e]) * 256);
            v = rp[q];
        }
        int arr = q >> 4, qq = q & 15;
        uint32_t* dp = (arr ? sAlo : sAhi) + e * 68 + qq * 4;
        *(uint4*)dp = v;
    }
    __syncthreads();

    // ---- MMA: 8 warps = 4 m-tiles (16 rows) x 2 n-halves (64 cols)
    int lane = threadIdx.x & 31;
    int wid  = threadIdx.x >> 5;
    int g    = lane >> 2;
    int tig  = lane & 3;
    int mtile = wid & 3;
    int nhalf = wid >> 2;
    int m0 = mtile * 16;

    float acc[8][4];
#pragma unroll
    for (int j = 0; j < 8; j++)
#pragma unroll
        for (int c = 0; c < 4; c++) acc[j][c] = 0.f;

    int aBase = (m0 + g) * 68 + tig;
    int bBase = (nhalf * 64 + g) * 68 + tig;

#pragma unroll
    for (int kc = 0; kc < 8; kc++) {
        int ko = kc * 8;
        uint32_t ah0 = sAhi[aBase + ko];
        uint32_t ah1 = sAhi[aBase + 544 + ko];
        uint32_t ah2 = sAhi[aBase + ko + 4];
        uint32_t ah3 = sAhi[aBase + 544 + ko + 4];
        uint32_t al0 = sAlo[aBase + ko];
        uint32_t al1 = sAlo[aBase + 544 + ko];
        uint32_t al2 = sAlo[aBase + ko + 4];
        uint32_t al3 = sAlo[aBase + 544 + ko + 4];
#pragma unroll
        for (int j = 0; j < 8; j++) {
            int bo = bBase + j * 544 + ko;
            uint32_t bh0 = sWhi[bo], bh1 = sWhi[bo + 4];
            uint32_t bl0 = sWlo[bo], bl1 = sWlo[bo + 4];
            mma16816(acc[j], al0, al1, al2, al3, bh0, bh1);  // lo*hi
            mma16816(acc[j], ah0, ah1, ah2, ah3, bl0, bl1);  // hi*lo
            mma16816(acc[j], ah0, ah1, ah2, ah3, bh0, bh1);  // hi*hi
        }
    }

    // ---- epilogue: smem bounce -> coalesced stores / red.v4
    __syncthreads();

    int colb = nhalf * 64 + tig * 2;
    int lr0 = m0 + g, lr1 = lr0 + 8;
#pragma unroll
    for (int j = 0; j < 8; j++) {
        int col = colb + j * 8;
        sOut[lr0 * OSTR + col]     = acc[j][0];
        sOut[lr0 * OSTR + col + 1] = acc[j][1];
        sOut[lr1 * OSTR + col]     = acc[j][2];
        sOut[lr1 * OSTR + col + 1] = acc[j][3];
    }
    __syncthreads();

    if (ROOTMODE) {
        for (int i = threadIdx.x; i < TILE_E * 32; i += 256) {
            int e = i >> 5, q = i & 31;
            int row = rowBase + e;
            if (row < N_NODES) {
                float4 v = *(const float4*)&sOut[e * OSTR + q * 4];
                v.x += sBias[q * 4];
                v.y += sBias[q * 4 + 1];
                v.z += sBias[q * 4 + 2];
                v.w += sBias[q * 4 + 3];
                *(float4*)(out + (size_t)row * D + q * 4) = v;
            }
        }
    } else {
        for (int i = threadIdx.x; i < TILE_E * 32; i += 256) {
            int e = i >> 5, q = i & 31;
            if (e < cnt) {
                float inv = sInv[e];
                float4 v = *(const float4*)&sOut[e * OSTR + q * 4];
                float* op = out + (size_t)sDst[e] * D + q * 4;
                red_v4(op, v.x * inv, v.y * inv, v.z * inv, v.w * inv);
            }
        }
    }
}

// ---------------- launch ----------------
extern "C" void kernel_launch(void* const* d_in, const int* in_sizes, int n_in,
                              void* d_out, int out_size) {
    const int*   x     = (const int*)d_in[0];
    const int*   edge  = (const int*)d_in[1];
    const int*   etype = (const int*)d_in[2];
    const float* emb   = (const float*)d_in[3];
    const float* w1    = (const float*)d_in[4];
    const float* root1 = (const float*)d_in[5];
    const float* b1    = (const float*)d_in[6];
    const float* w2    = (const float*)d_in[7];
    const float* root2 = (const float*)d_in[8];
    const float* b2    = (const float*)d_in[9];
    float* out = (float*)d_out;

    const int* src  = edge;
    const int* dstp = edge + E_EDGES;

    cudaFuncSetAttribute(k_mma<0>, cudaFuncAttributeMaxDynamicSharedMemorySize, SMEM_BYTES);
    cudaFuncSetAttribute(k_mma<1>, cudaFuncAttributeMaxDynamicSharedMemorySize, SMEM_BYTES);

    float *buf;
    __nv_bfloat16 *hs0, *hs1;
    __nv_bfloat16 *w1hi, *w1lo, *w2hi, *w2lo, *r1hi, *r1lo, *r2hi, *r2lo;
    {
        void* p;
        cudaGetSymbolAddress(&p, g_buf);  buf = (float*)p;
        cudaGetSymbolAddress(&p, g_hs0);  hs0 = (__nv_bfloat16*)p;
        cudaGetSymbolAddress(&p, g_hs1);  hs1 = (__nv_bfloat16*)p;
        cudaGetSymbolAddress(&p, g_w1hi); w1hi = (__nv_bfloat16*)p;
        cudaGetSymbolAddress(&p, g_w1lo); w1lo = (__nv_bfloat16*)p;
        cudaGetSymbolAddress(&p, g_w2hi); w2hi = (__nv_bfloat16*)p;
        cudaGetSymbolAddress(&p, g_w2lo); w2lo = (__nv_bfloat16*)p;
        cudaGetSymbolAddress(&p, g_r1hi); r1hi = (__nv_bfloat16*)p;
        cudaGetSymbolAddress(&p, g_r1lo); r1lo = (__nv_bfloat16*)p;
        cudaGetSymbolAddress(&p, g_r2hi); r2hi = (__nv_bfloat16*)p;
        cudaGetSymbolAddress(&p, g_r2lo); r2lo = (__nv_bfloat16*)p;
    }

    // 0: fused preprocessing
    k_mega<<<MEGA_BLOCKS, 256>>>(x, emb, etype, dstp, w1, w2, root1, root2);
    // 1: inverse degrees + scan + tile table
    k_inv_scan<<<(RELS * N_NODES + 255) / 256, 256>>>();
    // 2: relation-sorted permutation
    k_scatter<<<(E_EDGES + 255) / 256, 256>>>(etype);
    // 3: layer-1 root GEMM (PROFILED SLOT)
    k_mma<1><<<ROOT_TILES, 256, SMEM_BYTES>>>(hs0, r1hi, r1lo, b1, src, dstp, buf);
    // 4: layer-1 edge messages
    k_mma<0><<<MAX_TILES, 256, SMEM_BYTES>>>(hs0, w1hi, w1lo, b1, src, dstp, buf);
    // 5: relu + split for layer 2
    k_relusplit<<<GB, 256>>>();
    // 6: layer-2 root GEMM
    k_mma<1><<<ROOT_TILES, 256, SMEM_BYTES>>>(hs1, r2hi, r2lo, b2, src, dstp, out);
    // 7: layer-2 edge messages
    k_mma<0><<<MAX_TILES, 256, SMEM_BYTES>>>(hs1, w2hi, w2lo, b2, src, dstp, out);
}